// round 5
// baseline (speedup 1.0000x reference)
#include <cuda_runtime.h>
#include <math.h>

typedef unsigned int        u32;
typedef unsigned long long  u64;

#define HW     (512*512)
#define NB     4
#define NC     64
#define HID    128
#define NK     16
#define SOFTEN 10000.0f
#define EPSV   1e-8f

#define TILE        128
#define NTILES      (NB * HW / TILE)   // 8192
#define NCTA        148

// out layout: transformed_img [4,3,512,512] | m [4,16,512,512] | palette [4,16,3,1,1]
#define OFF_T  ((size_t)0)
#define OFF_M  ((size_t)NB * 3 * HW)
#define OFF_P  (OFF_M + (size_t)NB * NK * HW)

// ---- dynamic smem layout (bytes) ----
#define SM_AF     0            // A hi frags: [8mb][8ks][32lane][4reg] f32 = 32768
#define SM_AL     32768        // A lo frags: 32768
#define SM_W1F    65536        // W1 frag quads: [8ks][16nb][32lane][b0h,b1h,b0l,b1l] = 65536
#define SM_HS     131072       // h matrix: 128 rows x 136 words = 69632
#define SM_W2P    200704       // [64cp][16k] u64 = 8192
#define SM_B1     208896       // 512
#define SM_SLB    209408       // 128*17*4 = 8704
#define SM_SNUM   218112       // 192
#define SM_SDEN   218304       // 64
#define SMEM_BYTES 218400

// ---- scratch (no allocations allowed) ----
__device__ float         gNum[NB * NK * 3];
__device__ float         gDen[NB * NK];
__device__ float         gPal[NB * NK * 3];
__device__ unsigned char gArg[NB * HW];

// packed f32x2 (compiled fine in R2)
__device__ __forceinline__ u64 pack2(float lo, float hi) {
    u64 r; asm("mov.b64 %0, {%1, %2};" : "=l"(r) : "f"(lo), "f"(hi)); return r;
}
__device__ __forceinline__ void unpack2(float& lo, float& hi, u64 v) {
    asm("mov.b64 {%0, %1}, %2;" : "=f"(lo), "=f"(hi) : "l"(v));
}
#define FMA2(d, a, b, c) \
    asm("fma.rn.f32x2 %0, %1, %2, %3;" : "=l"(d) : "l"(a), "l"(b), "l"(c))

// warp-level tf32 MMA (sm_80 feature; runs on HMMA pipe on Blackwell)
#define MMA_TF32(d0, d1, d2, d3, a, b0, b1) \
    asm volatile("mma.sync.aligned.m16n8k8.row.col.f32.tf32.tf32.f32 " \
        "{%0,%1,%2,%3}, {%4,%5,%6,%7}, {%8,%9}, {%0,%1,%2,%3};" \
        : "+f"(d0), "+f"(d1), "+f"(d2), "+f"(d3) \
        : "r"((a).x), "r"((a).y), "r"((a).z), "r"((a).w), "r"(b0), "r"(b1))

// h-matrix word index: row stride 136 words; cols >= 64 shifted +8 words (bank pad)
__device__ __forceinline__ int hs_word(int px, int c) {
    return px * 136 + c + ((c >> 6) << 3);
}

__global__ void zero_kernel() {
    int t = threadIdx.x;
    if (t < NB * NK * 3) gNum[t] = 0.0f;
    if (t < NB * NK)     gDen[t] = 0.0f;
}

// ============================ main persistent kernel ============================
__global__ __launch_bounds__(256, 1) void main_kernel(
    const float* __restrict__ img,
    const float* __restrict__ feat,
    const float* __restrict__ W1,
    const float* __restrict__ b1,
    const float* __restrict__ W2,
    float* __restrict__ out)
{
    extern __shared__ char sm[];
    const int tid = threadIdx.x;
    const int wid = tid >> 5;
    const int lid = tid & 31;

    if (tid < NK * 3) *(float*)(sm + SM_SNUM + tid * 4) = 0.0f;
    if (tid < NK)     *(float*)(sm + SM_SDEN + tid * 4) = 0.0f;

    // --- stage weights once per CTA ---
    // W1 -> B-fragment quads (b0h, b1h, b0l, b1l); b0 = W1[n][ks*8 + (lane&3)], b1 at k+4
    for (int i = tid; i < 8 * 16 * 32; i += 256) {
        int ks = i >> 9, nb = (i >> 5) & 15, ln = i & 31;
        int n = nb * 8 + (ln >> 2);
        int k = ks * 8 + (ln & 3);
        float v0 = W1[n * NC + k];
        float v1 = W1[n * NC + k + 4];
        float h0 = __uint_as_float(__float_as_uint(v0) & 0xFFFFE000u);
        float h1 = __uint_as_float(__float_as_uint(v1) & 0xFFFFE000u);
        ((float4*)(sm + SM_W1F))[i] = make_float4(h0, h1, v0 - h0, v1 - h1);
    }
    // W2 pairs: W2p[cp][k] = (W2[k][2cp], W2[k][2cp+1])
    for (int i = tid; i < (HID / 2) * NK; i += 256) {
        int cp = i >> 4, k = i & 15;
        *(u64*)(sm + SM_W2P + (size_t)i * 8) = pack2(W2[k * HID + 2 * cp], W2[k * HID + 2 * cp + 1]);
    }
    if (tid < HID) *(float*)(sm + SM_B1 + tid * 4) = b1[tid];
    __syncthreads();

    const uint4* AfU  = (const uint4*)(sm + SM_AF);
    const uint4* AlU  = (const uint4*)(sm + SM_AL);
    const uint4* W1fU = (const uint4*)(sm + SM_W1F);
    float* Af = (float*)(sm + SM_AF);
    float* Al = (float*)(sm + SM_AL);
    float* Hs = (float*)(sm + SM_HS);

    const int bx = blockIdx.x;
    const int niter = (NTILES - 1 - bx) / NCTA + 1;

    const int mb0 = (wid & 3) * 2;        // this warp's two m-blocks
    const int nbB = (wid >> 2) * 8;       // this warp's eight n-blocks

    for (int it = 0; it < niter; it++) {
        const int t  = bx + NCTA * it;
        const int bb = t >> 11;                 // 2048 tiles per batch image
        const int p0 = (t & 2047) * TILE;

        // ---- load feat tile (128 px x 64 ch), split, scatter to A-fragment layout ----
        {
            const float* fb = feat + (size_t)bb * NC * HW + p0;
            for (int i4 = tid; i4 < TILE * NC / 4; i4 += 256) {
                int c = i4 >> 5, q = i4 & 31;
                float4 x = *(const float4*)(fb + (size_t)c * HW + q * 4);
                float v[4] = {x.x, x.y, x.z, x.w};
                int ks = c >> 3, kk = c & 7;
                int laneK = kk & 3, regK = (kk >> 2) << 1;
#pragma unroll
                for (int j = 0; j < 4; j++) {
                    int px = q * 4 + j;
                    int mb = px >> 4, rr = px & 15;
                    int lane = ((rr & 7) << 2) | laneK;
                    int reg  = (rr >> 3) | regK;
                    int idx = (((((mb << 3) | ks) << 5) | lane) << 2) | reg;
                    float hi = __uint_as_float(__float_as_uint(v[j]) & 0xFFFFE000u);
                    Af[idx] = hi;
                    Al[idx] = v[j] - hi;
                }
            }
        }
        __syncthreads();

        // ---- GEMM1 on tensor pipe: h[128px][128hid], 3xTF32 split ----
        float d[2][8][4];
#pragma unroll
        for (int i = 0; i < 2; i++)
#pragma unroll
            for (int j = 0; j < 8; j++)
#pragma unroll
                for (int r = 0; r < 4; r++) d[i][j][r] = 0.0f;

#pragma unroll
        for (int ks = 0; ks < 8; ks++) {
            uint4 ah0 = AfU[((mb0)     * 8 + ks) * 32 + lid];
            uint4 ah1 = AfU[((mb0 + 1) * 8 + ks) * 32 + lid];
            uint4 al0 = AlU[((mb0)     * 8 + ks) * 32 + lid];
            uint4 al1 = AlU[((mb0 + 1) * 8 + ks) * 32 + lid];
#pragma unroll
            for (int j = 0; j < 8; j++) {
                uint4 bq = W1fU[(ks * 16 + nbB + j) * 32 + lid];
                MMA_TF32(d[0][j][0], d[0][j][1], d[0][j][2], d[0][j][3], ah0, bq.x, bq.y);
                MMA_TF32(d[0][j][0], d[0][j][1], d[0][j][2], d[0][j][3], ah0, bq.z, bq.w);
                MMA_TF32(d[0][j][0], d[0][j][1], d[0][j][2], d[0][j][3], al0, bq.x, bq.y);
                MMA_TF32(d[1][j][0], d[1][j][1], d[1][j][2], d[1][j][3], ah1, bq.x, bq.y);
                MMA_TF32(d[1][j][0], d[1][j][1], d[1][j][2], d[1][j][3], ah1, bq.z, bq.w);
                MMA_TF32(d[1][j][0], d[1][j][1], d[1][j][2], d[1][j][3], al1, bq.x, bq.y);
            }
        }

        // ---- D frags -> Hs with bias + ReLU ----
#pragma unroll
        for (int i = 0; i < 2; i++) {
            int row = (mb0 + i) * 16 + (lid >> 2);
#pragma unroll
            for (int j = 0; j < 8; j++) {
                int n0 = (nbB + j) * 8 + (lid & 3) * 2;
                float2 bb2 = *(const float2*)(sm + SM_B1 + n0 * 4);
                float2 lo = make_float2(fmaxf(d[i][j][0] + bb2.x, 0.0f),
                                        fmaxf(d[i][j][1] + bb2.y, 0.0f));
                float2 hi = make_float2(fmaxf(d[i][j][2] + bb2.x, 0.0f),
                                        fmaxf(d[i][j][3] + bb2.y, 0.0f));
                *(float2*)(Hs + hs_word(row,     n0)) = lo;
                *(float2*)(Hs + hs_word(row + 8, n0)) = hi;
            }
        }
        __syncthreads();

        // ---- GEMV2 (exact fp32 via FFMA2) + softmax + argmax + palette accum ----
        const int px = (wid & 3) * 32 + lid;
        const int cb = (wid >> 2) * 64;

        u64 lp2[NK];
#pragma unroll
        for (int k = 0; k < NK; k++) lp2[k] = 0ULL;

        const float4* hrow = (const float4*)(Hs + hs_word(px, cb));
        const char* w2base = sm + SM_W2P + (size_t)(cb >> 1) * (NK * 8);
#pragma unroll 4
        for (int jj = 0; jj < 16; jj++) {
            float4 h4 = hrow[jj];
            u64 hp0 = pack2(h4.x, h4.y);
            u64 hp1 = pack2(h4.z, h4.w);
            const ulonglong2* wA = (const ulonglong2*)(w2base + (size_t)(2 * jj) * (NK * 8));
            const ulonglong2* wB = wA + 8;
#pragma unroll
            for (int q = 0; q < 8; q++) {
                ulonglong2 wa = wA[q];
                FMA2(lp2[2 * q],     hp0, wa.x, lp2[2 * q]);
                FMA2(lp2[2 * q + 1], hp0, wa.y, lp2[2 * q + 1]);
                ulonglong2 wb = wB[q];
                FMA2(lp2[2 * q],     hp1, wb.x, lp2[2 * q]);
                FMA2(lp2[2 * q + 1], hp1, wb.y, lp2[2 * q + 1]);
            }
        }
        float part[NK];
#pragma unroll
        for (int k = 0; k < NK; k++) {
            float a, b2; unpack2(a, b2, lp2[k]);
            part[k] = a + b2;
        }
        float* slb = (float*)(sm + SM_SLB);
        if (wid >= 4) {
#pragma unroll
            for (int k = 0; k < NK; k++) slb[px * 17 + k] = part[k];
        }
        __syncthreads();

        if (wid < 4) {
            float logits[NK];
#pragma unroll
            for (int k = 0; k < NK; k++) logits[k] = part[k] + slb[px * 17 + k];

            float mx = logits[0]; int am = 0;
#pragma unroll
            for (int k = 1; k < NK; k++) if (logits[k] > mx) { mx = logits[k]; am = k; }
            float e[NK], s = 0.0f;
#pragma unroll
            for (int k = 0; k < NK; k++) { e[k] = __expf(SOFTEN * (logits[k] - mx)); s += e[k]; }
            const float inv = 1.0f / s;

            const int p = p0 + px;
            float* mo = out + OFF_M + (size_t)bb * NK * HW + p;
#pragma unroll
            for (int k = 0; k < NK; k++) mo[(size_t)k * HW] = e[k] * inv;

            gArg[(size_t)bb * HW + p] = (unsigned char)am;

            const float* ip = img + (size_t)bb * 3 * HW + p;
            float* snum = (float*)(sm + SM_SNUM);
            float* sden = (float*)(sm + SM_SDEN);
            atomicAdd(&snum[am * 3 + 0], __ldg(ip));
            atomicAdd(&snum[am * 3 + 1], __ldg(ip + HW));
            atomicAdd(&snum[am * 3 + 2], __ldg(ip + 2 * HW));
            atomicAdd(&sden[am], 1.0f);
        }
        __syncthreads();
        if (tid < NK * 3) {
            float* snum = (float*)(sm + SM_SNUM);
            atomicAdd(&gNum[bb * NK * 3 + tid], snum[tid]);
            snum[tid] = 0.0f;
        }
        if (tid < NK) {
            float* sden = (float*)(sm + SM_SDEN);
            atomicAdd(&gDen[bb * NK + tid], sden[tid]);
            sden[tid] = 0.0f;
        }
        __syncthreads();
    }
}

__global__ void palette_kernel(float* __restrict__ out) {
    int t = threadIdx.x;
    if (t < NB * NK) {
        float d = gDen[t] + EPSV;
#pragma unroll
        for (int c = 0; c < 3; c++) {
            float v = gNum[t * 3 + c] / d;
            gPal[t * 3 + c] = v;
            out[OFF_P + (size_t)t * 3 + c] = v;
        }
    }
}

__global__ __launch_bounds__(256) void transform_kernel(float* __restrict__ out) {
    __shared__ float pal[NB * NK * 3];
    int t = threadIdx.x;
    if (t < NB * NK * 3) pal[t] = gPal[t];
    __syncthreads();

    int g = blockIdx.x * 256 + t;
    int b = g / HW;
    int p = g % HW;
    int am = gArg[g];

    const float* pp = &pal[(b * NK + am) * 3];
    float* op = out + OFF_T + (size_t)b * 3 * HW + p;
    op[0]              = pp[0];
    op[(size_t)HW]     = pp[1];
    op[(size_t)2 * HW] = pp[2];
}

extern "C" void kernel_launch(void* const* d_in, const int* in_sizes, int n_in,
                              void* d_out, int out_size) {
    const float* img  = (const float*)d_in[0];
    const float* feat = (const float*)d_in[1];
    const float* W1   = (const float*)d_in[2];
    const float* b1   = (const float*)d_in[3];
    const float* W2   = (const float*)d_in[4];
    float* out = (float*)d_out;

    cudaFuncSetAttribute(main_kernel, cudaFuncAttributeMaxDynamicSharedMemorySize, SMEM_BYTES);

    zero_kernel<<<1, 256>>>();
    main_kernel<<<NCTA, 256, SMEM_BYTES>>>(img, feat, W1, b1, W2, out);
    palette_kernel<<<1, 64>>>(out);
    transform_kernel<<<NB * HW / 256, 256>>>(out);
}

// round 7
// speedup vs baseline: 1.3354x; 1.3354x over previous
#include <cuda_runtime.h>
#include <math.h>

typedef unsigned int        u32;
typedef unsigned long long  u64;

#define HW     (512*512)
#define NB     4
#define NC     64
#define HID    128
#define NK     16
#define SOFTEN 10000.0f
#define EPSV   1e-8f

#define TILE        128
#define NTILES      (NB * HW / TILE)   // 8192
#define NCTA        148

// out layout: transformed_img [4,3,512,512] | m [4,16,512,512] | palette [4,16,3,1,1]
#define OFF_T  ((size_t)0)
#define OFF_M  ((size_t)NB * 3 * HW)
#define OFF_P  (OFF_M + (size_t)NB * NK * HW)

// ---- dynamic smem layout (bytes) ----
#define SM_A      0            // 2 bufs x [64 c-rows x 512B] = 65536
#define SM_H      65536        // 128 px-rows x 544B (136 f32) = 69632
#define SM_W1P    135168       // [64 c][64 o-pair u64] = 32768
#define SM_W2P    167936       // [64 cp][16 k] u64 = 8192
#define SM_B1     176128       // 512
#define SM_SLB    176640       // 128*17*4 = 8704
#define SM_SNUM   185344       // 192
#define SM_SDEN   185536       // 64
#define SMEM_BYTES 185600

// ---- scratch (no allocations allowed) ----
__device__ float         gNum[NB * NK * 3];
__device__ float         gDen[NB * NK];
__device__ float         gPal[NB * NK * 3];
__device__ unsigned char gArg[NB * HW];

// packed f32x2
__device__ __forceinline__ u64 pack2(float lo, float hi) {
    u64 r; asm("mov.b64 %0, {%1, %2};" : "=l"(r) : "f"(lo), "f"(hi)); return r;
}
__device__ __forceinline__ void unpack2(float& lo, float& hi, u64 v) {
    asm("mov.b64 {%0, %1}, %2;" : "=f"(lo), "=f"(hi) : "l"(v));
}
#define FMA2(d, a, b, c) \
    asm("fma.rn.f32x2 %0, %1, %2, %3;" : "=l"(d) : "l"(a), "l"(b), "l"(c))

__device__ __forceinline__ u32 smem_u32(const void* p) {
    u32 a;
    asm("{ .reg .u64 t; cvta.to.shared.u64 t, %1; cvt.u32.u64 %0, t; }" : "=r"(a) : "l"(p));
    return a;
}
#define CP_ASYNC16(dst, src) \
    asm volatile("cp.async.ca.shared.global [%0], [%1], 16;" :: "r"(dst), "l"(src) : "memory")
#define CP_COMMIT()  asm volatile("cp.async.commit_group;" ::: "memory")
#define CP_WAIT0()   asm volatile("cp.async.wait_group 0;" ::: "memory")

// A-row chunk swizzle (permutation): spreads even/odd 16B chunks over bank-quads
__device__ __forceinline__ int a_pos(int ci) { return ci ^ ((ci >> 3) & 1); }

__global__ void zero_kernel() {
    int t = threadIdx.x;
    if (t < NB * NK * 3) gNum[t] = 0.0f;
    if (t < NB * NK)     gDen[t] = 0.0f;
}

// ============================ main persistent kernel ============================
__global__ __launch_bounds__(256, 1) void main_kernel(
    const float* __restrict__ img,
    const float* __restrict__ feat,
    const float* __restrict__ W1,
    const float* __restrict__ b1,
    const float* __restrict__ W2,
    float* __restrict__ out)
{
    extern __shared__ char sm[];
    const int tid = threadIdx.x;
    const int wid = tid >> 5;
    const int lid = tid & 31;
    const int tx  = tid & 15;        // px group: px0 = 8*tx
    const int ty  = tid >> 4;        // o group:  o0  = 8*ty
    const int px0 = tx * 8;

    if (tid < NK * 3) *(float*)(sm + SM_SNUM + tid * 4) = 0.0f;
    if (tid < NK)     *(float*)(sm + SM_SDEN + tid * 4) = 0.0f;

    // --- stage weights once per CTA ---
    // W1p[c][op] = (W1[2op][c], W1[2op+1][c])
    for (int i = tid; i < NC * (HID / 2); i += 256) {
        int c = i >> 6, op = i & 63;
        *(u64*)(sm + SM_W1P + (size_t)c * 512 + (size_t)op * 8) =
            pack2(W1[(2 * op) * NC + c], W1[(2 * op + 1) * NC + c]);
    }
    // W2p[cp][k] = (W2[k][2cp], W2[k][2cp+1])
    for (int i = tid; i < (HID / 2) * NK; i += 256) {
        int cp = i >> 4, k = i & 15;
        *(u64*)(sm + SM_W2P + (size_t)i * 8) = pack2(W2[k * HID + 2 * cp], W2[k * HID + 2 * cp + 1]);
    }
    if (tid < HID) *(float*)(sm + SM_B1 + tid * 4) = b1[tid];

    __syncthreads();   // *** R6 bug fix: bias/weights must be visible before bia load ***

    const int bx = blockIdx.x;
    const int niter = (NTILES - 1 - bx) / NCTA + 1;

    const u32 smA = smem_u32(sm + SM_A);

    // prologue: prefetch A tile 0
    {
        const int t0 = bx;
        const float* fb = feat + (size_t)(t0 >> 11) * NC * HW + (t0 & 2047) * TILE;
#pragma unroll
        for (int r = 0; r < 8; r++) {
            int i = tid + 256 * r;
            int c = i >> 5, ci = i & 31;
            CP_ASYNC16(smA + c * 512 + a_pos(ci) * 16, fb + (size_t)c * HW + ci * 4);
        }
        CP_COMMIT();
    }

    const u32 offA0 = (u32)(a_pos(2 * tx)     * 16);
    const u32 offA1 = (u32)(a_pos(2 * tx + 1) * 16);
    const u32 offW  = (u32)(ty * 32);

    // bias for this thread's 8 o values
    float2 bia[4];
#pragma unroll
    for (int j = 0; j < 4; j++) bia[j] = ((const float2*)(sm + SM_B1 + ty * 32))[j];

    for (int it = 0; it < niter; it++) {
        const int t  = bx + NCTA * it;
        const int bb = t >> 11;
        const int p0 = (t & 2047) * TILE;
        const int buf = it & 1;

        CP_WAIT0();
        __syncthreads();   // A[cur] visible to all; prev epilogue done

        // prefetch next tile while we compute
        if (it + 1 < niter) {
            const int tn = bx + NCTA * (it + 1);
            const float* fb = feat + (size_t)(tn >> 11) * NC * HW + (tn & 2047) * TILE;
            const u32 dst = smA + (buf ^ 1) * 32768;
#pragma unroll
            for (int r = 0; r < 8; r++) {
                int i = tid + 256 * r;
                int c = i >> 5, ci = i & 31;
                CP_ASYNC16(dst + c * 512 + a_pos(ci) * 16, fb + (size_t)c * HW + ci * 4);
            }
            CP_COMMIT();
        }

        // ---- GEMM1: acc[8px][4 o-pairs], exact fp32 via FMA2 ----
        u64 acc[8][4];
#pragma unroll
        for (int i = 0; i < 8; i++)
#pragma unroll
            for (int j = 0; j < 4; j++) acc[i][j] = 0ULL;

        const char* Ab = sm + SM_A + buf * 32768;
        const char* Wb = sm + SM_W1P;
#pragma unroll 4
        for (int c = 0; c < NC; c++) {
            float4 aA = *(const float4*)(Ab + c * 512 + offA0);   // px0..px0+3
            float4 aB = *(const float4*)(Ab + c * 512 + offA1);   // px0+4..px0+7
            ulonglong2 w01 = *(const ulonglong2*)(Wb + c * 512 + offW);
            ulonglong2 w23 = *(const ulonglong2*)(Wb + c * 512 + offW + 16);
            u64 ad;
            ad = pack2(aA.x, aA.x);
            FMA2(acc[0][0], ad, w01.x, acc[0][0]); FMA2(acc[0][1], ad, w01.y, acc[0][1]);
            FMA2(acc[0][2], ad, w23.x, acc[0][2]); FMA2(acc[0][3], ad, w23.y, acc[0][3]);
            ad = pack2(aA.y, aA.y);
            FMA2(acc[1][0], ad, w01.x, acc[1][0]); FMA2(acc[1][1], ad, w01.y, acc[1][1]);
            FMA2(acc[1][2], ad, w23.x, acc[1][2]); FMA2(acc[1][3], ad, w23.y, acc[1][3]);
            ad = pack2(aA.z, aA.z);
            FMA2(acc[2][0], ad, w01.x, acc[2][0]); FMA2(acc[2][1], ad, w01.y, acc[2][1]);
            FMA2(acc[2][2], ad, w23.x, acc[2][2]); FMA2(acc[2][3], ad, w23.y, acc[2][3]);
            ad = pack2(aA.w, aA.w);
            FMA2(acc[3][0], ad, w01.x, acc[3][0]); FMA2(acc[3][1], ad, w01.y, acc[3][1]);
            FMA2(acc[3][2], ad, w23.x, acc[3][2]); FMA2(acc[3][3], ad, w23.y, acc[3][3]);
            ad = pack2(aB.x, aB.x);
            FMA2(acc[4][0], ad, w01.x, acc[4][0]); FMA2(acc[4][1], ad, w01.y, acc[4][1]);
            FMA2(acc[4][2], ad, w23.x, acc[4][2]); FMA2(acc[4][3], ad, w23.y, acc[4][3]);
            ad = pack2(aB.y, aB.y);
            FMA2(acc[5][0], ad, w01.x, acc[5][0]); FMA2(acc[5][1], ad, w01.y, acc[5][1]);
            FMA2(acc[5][2], ad, w23.x, acc[5][2]); FMA2(acc[5][3], ad, w23.y, acc[5][3]);
            ad = pack2(aB.z, aB.z);
            FMA2(acc[6][0], ad, w01.x, acc[6][0]); FMA2(acc[6][1], ad, w01.y, acc[6][1]);
            FMA2(acc[6][2], ad, w23.x, acc[6][2]); FMA2(acc[6][3], ad, w23.y, acc[6][3]);
            ad = pack2(aB.w, aB.w);
            FMA2(acc[7][0], ad, w01.x, acc[7][0]); FMA2(acc[7][1], ad, w01.y, acc[7][1]);
            FMA2(acc[7][2], ad, w23.x, acc[7][2]); FMA2(acc[7][3], ad, w23.y, acc[7][3]);
        }

        // ---- bias + ReLU + store h (swizzled, px-major stride 136 f32) ----
#pragma unroll
        for (int i = 0; i < 8; i++) {
            char* hrow = sm + SM_H + (size_t)(px0 + i) * 544;
            int s0 = ((2 * ty)     ^ (tx & 7)) << 4;
            int s1 = ((2 * ty + 1) ^ (tx & 7)) << 4;
            float a0, a1, a2, a3;
            unpack2(a0, a1, acc[i][0]); unpack2(a2, a3, acc[i][1]);
            *(float4*)(hrow + s0) = make_float4(
                fmaxf(a0 + bia[0].x, 0.0f), fmaxf(a1 + bia[0].y, 0.0f),
                fmaxf(a2 + bia[1].x, 0.0f), fmaxf(a3 + bia[1].y, 0.0f));
            unpack2(a0, a1, acc[i][2]); unpack2(a2, a3, acc[i][3]);
            *(float4*)(hrow + s1) = make_float4(
                fmaxf(a0 + bia[2].x, 0.0f), fmaxf(a1 + bia[2].y, 0.0f),
                fmaxf(a2 + bia[3].x, 0.0f), fmaxf(a3 + bia[3].y, 0.0f));
        }
        __syncthreads();

        // ---- GEMV2 + softmax + argmax + palette accum ----
        const int px  = (wid & 3) * 32 + lid;
        const int cbc = (wid >> 2) * 16;           // h chunk base (o = 4*chunk)
        const int sw  = (px >> 3) & 7;

        u64 lp2[NK];
#pragma unroll
        for (int k = 0; k < NK; k++) lp2[k] = 0ULL;

        const char* hbase  = sm + SM_H + (size_t)px * 544;
        const char* w2base = sm + SM_W2P + (size_t)(cbc * 2) * (NK * 8);
#pragma unroll 4
        for (int jj = 0; jj < 16; jj++) {
            float4 h4 = *(const float4*)(hbase + (((cbc + jj) ^ sw) << 4));
            u64 hp0 = pack2(h4.x, h4.y);
            u64 hp1 = pack2(h4.z, h4.w);
            const ulonglong2* wA = (const ulonglong2*)(w2base + (size_t)(2 * jj) * (NK * 8));
            const ulonglong2* wB = wA + 8;
#pragma unroll
            for (int q = 0; q < 8; q++) {
                ulonglong2 wa = wA[q];
                FMA2(lp2[2 * q],     hp0, wa.x, lp2[2 * q]);
                FMA2(lp2[2 * q + 1], hp0, wa.y, lp2[2 * q + 1]);
                ulonglong2 wb = wB[q];
                FMA2(lp2[2 * q],     hp1, wb.x, lp2[2 * q]);
                FMA2(lp2[2 * q + 1], hp1, wb.y, lp2[2 * q + 1]);
            }
        }
        float part[NK];
#pragma unroll
        for (int k = 0; k < NK; k++) {
            float a, b2; unpack2(a, b2, lp2[k]);
            part[k] = a + b2;
        }
        float* slb = (float*)(sm + SM_SLB);
        if (wid >= 4) {
#pragma unroll
            for (int k = 0; k < NK; k++) slb[px * 17 + k] = part[k];
        }
        __syncthreads();

        if (wid < 4) {
            float logits[NK];
#pragma unroll
            for (int k = 0; k < NK; k++) logits[k] = part[k] + slb[px * 17 + k];

            float mx = logits[0]; int am = 0;
#pragma unroll
            for (int k = 1; k < NK; k++) if (logits[k] > mx) { mx = logits[k]; am = k; }
            float e[NK], s = 0.0f;
#pragma unroll
            for (int k = 0; k < NK; k++) { e[k] = __expf(SOFTEN * (logits[k] - mx)); s += e[k]; }
            const float inv = 1.0f / s;

            const int p = p0 + px;
            float* mo = out + OFF_M + (size_t)bb * NK * HW + p;
#pragma unroll
            for (int k = 0; k < NK; k++) mo[(size_t)k * HW] = e[k] * inv;

            gArg[(size_t)bb * HW + p] = (unsigned char)am;

            const float* ip = img + (size_t)bb * 3 * HW + p;
            float* snum = (float*)(sm + SM_SNUM);
            float* sden = (float*)(sm + SM_SDEN);
            atomicAdd(&snum[am * 3 + 0], __ldg(ip));
            atomicAdd(&snum[am * 3 + 1], __ldg(ip + HW));
            atomicAdd(&snum[am * 3 + 2], __ldg(ip + 2 * HW));
            atomicAdd(&sden[am], 1.0f);
        }
        __syncthreads();
        if (tid < NK * 3) {
            float* snum = (float*)(sm + SM_SNUM);
            atomicAdd(&gNum[bb * NK * 3 + tid], snum[tid]);
            snum[tid] = 0.0f;
        }
        if (tid < NK) {
            float* sden = (float*)(sm + SM_SDEN);
            atomicAdd(&gDen[bb * NK + tid], sden[tid]);
            sden[tid] = 0.0f;
        }
        __syncthreads();
    }
}

__global__ void palette_kernel(float* __restrict__ out) {
    int t = threadIdx.x;
    if (t < NB * NK) {
        float d = gDen[t] + EPSV;
#pragma unroll
        for (int c = 0; c < 3; c++) {
            float v = gNum[t * 3 + c] / d;
            gPal[t * 3 + c] = v;
            out[OFF_P + (size_t)t * 3 + c] = v;
        }
    }
}

__global__ __launch_bounds__(256) void transform_kernel(float* __restrict__ out) {
    __shared__ float pal[NB * NK * 3];
    int t = threadIdx.x;
    if (t < NB * NK * 3) pal[t] = gPal[t];
    __syncthreads();

    int g = blockIdx.x * 256 + t;
    int b = g / HW;
    int p = g % HW;
    int am = gArg[g];

    const float* pp = &pal[(b * NK + am) * 3];
    float* op = out + OFF_T + (size_t)b * 3 * HW + p;
    op[0]              = pp[0];
    op[(size_t)HW]     = pp[1];
    op[(size_t)2 * HW] = pp[2];
}

extern "C" void kernel_launch(void* const* d_in, const int* in_sizes, int n_in,
                              void* d_out, int out_size) {
    const float* img  = (const float*)d_in[0];
    const float* feat = (const float*)d_in[1];
    const float* W1   = (const float*)d_in[2];
    const float* b1   = (const float*)d_in[3];
    const float* W2   = (const float*)d_in[4];
    float* out = (float*)d_out;

    cudaFuncSetAttribute(main_kernel, cudaFuncAttributeMaxDynamicSharedMemorySize, SMEM_BYTES);

    zero_kernel<<<1, 256>>>();
    main_kernel<<<NCTA, 256, SMEM_BYTES>>>(img, feat, W1, b1, W2, out);
    palette_kernel<<<1, 64>>>(out);
    transform_kernel<<<NB * HW / 256, 256>>>(out);
}

// round 9
// speedup vs baseline: 2.3150x; 1.7336x over previous
#include <cuda_runtime.h>
#include <cuda_fp16.h>
#include <math.h>

typedef unsigned int        u32;
typedef unsigned long long  u64;

#define HW     (512*512)
#define NB     4
#define NC     64
#define HID    128
#define NK     16
#define SOFTEN 10000.0f
#define EPSV   1e-8f

#define TILE        128
#define NTILES      (NB * HW / TILE)   // 8192
#define NCTA        148

// out layout: transformed_img [4,3,512,512] | m [4,16,512,512] | palette [4,16,3,1,1]
#define OFF_T  ((size_t)0)
#define OFF_M  ((size_t)NB * 3 * HW)
#define OFF_P  (OFF_M + (size_t)NB * NK * HW)

// ---- dynamic smem layout (bytes) ----
#define A_ROW     528                          // 132 f32 per c-row (128 px + pad)
#define A_BUF     (NC * A_ROW)                 // 33792
#define SM_A      0                            // 2 bufs = 67584
#define SM_W1F    67584                        // 4ks x 16nb x 32 lane x uint4 = 32768
#define SM_W2F    100352                       // 8ks x 2nb x 32 lane x uint4 = 8192
#define SM_SLB    108544                       // 2 x 128 x 20 f32 = 20480
#define SM_SNUM   129024                       // 192
#define SM_SDEN   129216                       // 64
#define SMEM_BYTES 129280

// ---- scratch (no allocations allowed) ----
__device__ float         gNum[NB * NK * 3];
__device__ float         gDen[NB * NK];
__device__ float         gPal[NB * NK * 3];
__device__ unsigned char gArg[NB * HW];

__device__ __forceinline__ u32 smem_u32(const void* p) {
    u32 a;
    asm("{ .reg .u64 t; cvta.to.shared.u64 t, %1; cvt.u32.u64 %0, t; }" : "=r"(a) : "l"(p));
    return a;
}
#define CP_ASYNC16(dst, src) \
    asm volatile("cp.async.ca.shared.global [%0], [%1], 16;" :: "r"(dst), "l"(src) : "memory")
#define CP_COMMIT()  asm volatile("cp.async.commit_group;" ::: "memory")
#define CP_WAIT0()   asm volatile("cp.async.wait_group 0;" ::: "memory")

// fp16 m16n8k16 HMMA, f32 accumulate
__device__ __forceinline__ void mma16(float d[4], u32 a0, u32 a1, u32 a2, u32 a3,
                                      u32 b0, u32 b1) {
    asm volatile(
        "mma.sync.aligned.m16n8k16.row.col.f32.f16.f16.f32 "
        "{%0,%1,%2,%3},{%4,%5,%6,%7},{%8,%9},{%0,%1,%2,%3};"
        : "+f"(d[0]), "+f"(d[1]), "+f"(d[2]), "+f"(d[3])
        : "r"(a0), "r"(a1), "r"(a2), "r"(a3), "r"(b0), "r"(b1));
}

// exact 2-way fp16 split of a float pair: (x,y) -> hi fp16x2 + lo fp16x2
__device__ __forceinline__ void split2(float x, float y, u32& hi, u32& lo) {
    __half2 h = __floats2half2_rn(x, y);
    float2  b = __half22float2(h);
    __half2 l = __floats2half2_rn(x - b.x, y - b.y);
    hi = *(u32*)&h;
    lo = *(u32*)&l;
}

__global__ void zero_kernel() {
    int t = threadIdx.x;
    if (t < NB * NK * 3) gNum[t] = 0.0f;
    if (t < NB * NK)     gDen[t] = 0.0f;
}

// ============================ main persistent kernel ============================
__global__ __launch_bounds__(256, 1) void main_kernel(
    const float* __restrict__ img,
    const float* __restrict__ feat,
    const float* __restrict__ W1,
    const float* __restrict__ b1,
    const float* __restrict__ W2,
    float* __restrict__ out)
{
    extern __shared__ char sm[];
    const int tid = threadIdx.x;
    const int wid = tid >> 5;
    const int lid = tid & 31;
    const int mwarp = wid & 3;        // px range: mwarp*32 .. +31
    const int nwarp = wid >> 2;       // o range:  nwarp*64 .. +63
    const int lq = lid & 3;           // threadID-in-group
    const int lg = lid >> 2;          // groupID (row within 8)

    if (tid < NK * 3) *(float*)(sm + SM_SNUM + tid * 4) = 0.0f;
    if (tid < NK)     *(float*)(sm + SM_SDEN + tid * 4) = 0.0f;

    // ---- stage W1 fragments (once per CTA): [ks][nb][lane] uint4 (b0h,b1h,b0l,b1l)
    {
        uint4* W1F = (uint4*)(sm + SM_W1F);
        for (int e = tid; e < 4 * 16 * 32; e += 256) {
            int ks = e >> 9, nb = (e >> 5) & 15, ln = e & 31;
            int o  = nb * 8 + (ln >> 2);
            int c0 = ks * 16 + 2 * (ln & 3);
            u32 b0h, b0l, b1h, b1l;
            split2(W1[o * NC + c0],     W1[o * NC + c0 + 1], b0h, b0l);
            split2(W1[o * NC + c0 + 8], W1[o * NC + c0 + 9], b1h, b1l);
            W1F[e] = make_uint4(b0h, b1h, b0l, b1l);
        }
        uint4* W2F = (uint4*)(sm + SM_W2F);
        for (int e = tid; e < 8 * 2 * 32; e += 256) {
            int ks2 = e >> 6, nbk = (e >> 5) & 1, ln = e & 31;
            int cls = nbk * 8 + (ln >> 2);
            int o0  = ks2 * 16 + 2 * (ln & 3);
            u32 b0h, b0l, b1h, b1l;
            split2(W2[cls * HID + o0],     W2[cls * HID + o0 + 1], b0h, b0l);
            split2(W2[cls * HID + o0 + 8], W2[cls * HID + o0 + 9], b1h, b1l);
            W2F[e] = make_uint4(b0h, b1h, b0l, b1l);
        }
    }

    // per-lane bias pairs for the warp's 8 o-blocks (o = nwarp*64 + j*8 + 2*lq + {0,1})
    float2 bias2[8];
#pragma unroll
    for (int j = 0; j < 8; j++)
        bias2[j] = *(const float2*)(b1 + nwarp * 64 + j * 8 + 2 * lq);

    __syncthreads();   // W1F/W2F + snum visible

    const int bx = blockIdx.x;
    const int niter = (NTILES - 1 - bx) / NCTA + 1;
    const u32 smA = smem_u32(sm + SM_A);

    // prologue: prefetch tile 0 (c-major fp32, row stride 528B)
    {
        const int t0 = bx;
        const float* fb = feat + (size_t)(t0 >> 11) * NC * HW + (t0 & 2047) * TILE;
#pragma unroll
        for (int r = 0; r < 8; r++) {
            int i = tid + 256 * r;
            int c = i >> 5, ci = i & 31;
            CP_ASYNC16(smA + c * A_ROW + ci * 16, fb + (size_t)c * HW + ci * 4);
        }
        CP_COMMIT();
    }

    const uint4* W1F = (const uint4*)(sm + SM_W1F);
    const uint4* W2F = (const uint4*)(sm + SM_W2F);
    float* slb = (float*)(sm + SM_SLB);

    for (int it = 0; it < niter; it++) {
        const int t  = bx + NCTA * it;
        const int bb = t >> 11;
        const int p0 = (t & 2047) * TILE;
        const int buf = it & 1;

        CP_WAIT0();
        __syncthreads();

        if (it + 1 < niter) {
            const int tn = bx + NCTA * (it + 1);
            const float* fb = feat + (size_t)(tn >> 11) * NC * HW + (tn & 2047) * TILE;
            const u32 dst = smA + (buf ^ 1) * A_BUF;
#pragma unroll
            for (int r = 0; r < 8; r++) {
                int i = tid + 256 * r;
                int c = i >> 5, ci = i & 31;
                CP_ASYNC16(dst + c * A_ROW + ci * 16, fb + (size_t)c * HW + ci * 4);
            }
            CP_COMMIT();
        }

        // ================= GEMM1 (tensor): h = feat * W1^T, fp16 3-term split ======
        const float* Ab = (const float*)(sm + SM_A + buf * A_BUF);
        float d[2][8][4];
#pragma unroll
        for (int mb = 0; mb < 2; mb++)
#pragma unroll
            for (int j = 0; j < 8; j++)
#pragma unroll
                for (int r = 0; r < 4; r++) d[mb][j][r] = 0.0f;

#pragma unroll
        for (int ks = 0; ks < 4; ks++) {
            u32 ah[2][4], al[2][4];
#pragma unroll
            for (int mb = 0; mb < 2; mb++) {
                const int pxr = mwarp * 32 + mb * 16 + lg;
                const int c0  = ks * 16 + 2 * lq;
                float f0 = Ab[c0 * 132 + pxr],       f1 = Ab[(c0 + 1) * 132 + pxr];
                float f2 = Ab[c0 * 132 + pxr + 8],   f3 = Ab[(c0 + 1) * 132 + pxr + 8];
                float f4 = Ab[(c0 + 8) * 132 + pxr], f5 = Ab[(c0 + 9) * 132 + pxr];
                float f6 = Ab[(c0 + 8) * 132 + pxr + 8], f7 = Ab[(c0 + 9) * 132 + pxr + 8];
                split2(f0, f1, ah[mb][0], al[mb][0]);
                split2(f2, f3, ah[mb][1], al[mb][1]);
                split2(f4, f5, ah[mb][2], al[mb][2]);
                split2(f6, f7, ah[mb][3], al[mb][3]);
            }
#pragma unroll
            for (int j = 0; j < 8; j++) {
                uint4 bq = W1F[(ks * 16 + nwarp * 8 + j) * 32 + lid];
#pragma unroll
                for (int mb = 0; mb < 2; mb++) {
                    mma16(d[mb][j], ah[mb][0], ah[mb][1], ah[mb][2], ah[mb][3], bq.x, bq.y);
                    mma16(d[mb][j], ah[mb][0], ah[mb][1], ah[mb][2], ah[mb][3], bq.z, bq.w);
                    mma16(d[mb][j], al[mb][0], al[mb][1], al[mb][2], al[mb][3], bq.x, bq.y);
                }
            }
        }

        // ================= GEMM2 (tensor): logits = relu(h+b1) * W2^T ==============
        float l2[2][2][4];
#pragma unroll
        for (int mb = 0; mb < 2; mb++)
#pragma unroll
            for (int nbk = 0; nbk < 2; nbk++)
#pragma unroll
                for (int r = 0; r < 4; r++) l2[mb][nbk][r] = 0.0f;

#pragma unroll
        for (int s = 0; s < 4; s++) {
            const int ks2g = nwarp * 4 + s;
#pragma unroll
            for (int mb = 0; mb < 2; mb++) {
                u32 a0h, a0l, a1h, a1l, a2h, a2l, a3h, a3l;
                {
                    const int j = 2 * s;
                    float r0 = fmaxf(d[mb][j][0] + bias2[j].x, 0.0f);
                    float r1 = fmaxf(d[mb][j][1] + bias2[j].y, 0.0f);
                    float r2 = fmaxf(d[mb][j][2] + bias2[j].x, 0.0f);
                    float r3 = fmaxf(d[mb][j][3] + bias2[j].y, 0.0f);
                    split2(r0, r1, a0h, a0l);
                    split2(r2, r3, a1h, a1l);
                }
                {
                    const int j = 2 * s + 1;
                    float r0 = fmaxf(d[mb][j][0] + bias2[j].x, 0.0f);
                    float r1 = fmaxf(d[mb][j][1] + bias2[j].y, 0.0f);
                    float r2 = fmaxf(d[mb][j][2] + bias2[j].x, 0.0f);
                    float r3 = fmaxf(d[mb][j][3] + bias2[j].y, 0.0f);
                    split2(r0, r1, a2h, a2l);
                    split2(r2, r3, a3h, a3l);
                }
#pragma unroll
                for (int nbk = 0; nbk < 2; nbk++) {
                    uint4 w = W2F[(ks2g * 2 + nbk) * 32 + lid];
                    mma16(l2[mb][nbk], a0h, a1h, a2h, a3h, w.x, w.y);
                    mma16(l2[mb][nbk], a0h, a1h, a2h, a3h, w.z, w.w);
                    mma16(l2[mb][nbk], a0l, a1l, a2l, a3l, w.x, w.y);
                }
            }
        }

        // ---- write partial logits (over this warp's 64 o) to slb[nwarp] ----
#pragma unroll
        for (int mb = 0; mb < 2; mb++) {
            const int r1 = mwarp * 32 + mb * 16 + lg;
#pragma unroll
            for (int nbk = 0; nbk < 2; nbk++) {
                const int cls = nbk * 8 + 2 * lq;
                *(float2*)&slb[(nwarp * 128 + r1) * 20 + cls] =
                    make_float2(l2[mb][nbk][0], l2[mb][nbk][1]);
                *(float2*)&slb[(nwarp * 128 + r1 + 8) * 20 + cls] =
                    make_float2(l2[mb][nbk][2], l2[mb][nbk][3]);
            }
        }
        __syncthreads();

        // ================= epilogue: 2 lanes per pixel =============================
        {
            const int pxl = wid * 16 + (lid & 15);
            const int kh  = lid >> 4;              // k-half: 0 -> k 0..7, 1 -> 8..15
            const int p   = p0 + pxl;

            float4 vA0 = *(float4*)&slb[pxl * 20 + kh * 8];
            float4 vA1 = *(float4*)&slb[pxl * 20 + kh * 8 + 4];
            float4 vB0 = *(float4*)&slb[(128 + pxl) * 20 + kh * 8];
            float4 vB1 = *(float4*)&slb[(128 + pxl) * 20 + kh * 8 + 4];
            float v[8] = {vA0.x + vB0.x, vA0.y + vB0.y, vA0.z + vB0.z, vA0.w + vB0.w,
                          vA1.x + vB1.x, vA1.y + vB1.y, vA1.z + vB1.z, vA1.w + vB1.w};

            float mx = v[0];
            int   am = kh * 8;
#pragma unroll
            for (int k = 1; k < 8; k++)
                if (v[k] > mx) { mx = v[k]; am = kh * 8 + k; }

            float mo_ = __shfl_xor_sync(0xffffffffu, mx, 16);
            int   ao_ = __shfl_xor_sync(0xffffffffu, am, 16);
            bool take = (mo_ > mx) || (mo_ == mx && ao_ < am);
            float gmax = take ? mo_ : mx;
            int   gam  = take ? ao_ : am;

            float e[8], s = 0.0f;
#pragma unroll
            for (int k = 0; k < 8; k++) { e[k] = __expf(SOFTEN * (v[k] - gmax)); s += e[k]; }
            s += __shfl_xor_sync(0xffffffffu, s, 16);
            const float inv = 1.0f / s;

            float* mo = out + OFF_M + (size_t)bb * NK * HW + (size_t)kh * 8 * HW + p;
#pragma unroll
            for (int k = 0; k < 8; k++) mo[(size_t)k * HW] = e[k] * inv;

            if (kh == 0) {
                gArg[(size_t)bb * HW + p] = (unsigned char)gam;
                const float* ip = img + (size_t)bb * 3 * HW + p;
                float* snum = (float*)(sm + SM_SNUM);
                float* sden = (float*)(sm + SM_SDEN);
                atomicAdd(&snum[gam * 3 + 0], __ldg(ip));
                atomicAdd(&snum[gam * 3 + 1], __ldg(ip + HW));
                atomicAdd(&snum[gam * 3 + 2], __ldg(ip + 2 * HW));
                atomicAdd(&sden[gam], 1.0f);
            }
        }
        __syncthreads();
        if (tid < NK * 3) {
            float* snum = (float*)(sm + SM_SNUM);
            atomicAdd(&gNum[bb * NK * 3 + tid], snum[tid]);
            snum[tid] = 0.0f;
        }
        if (tid < NK) {
            float* sden = (float*)(sm + SM_SDEN);
            atomicAdd(&gDen[bb * NK + tid], sden[tid]);
            sden[tid] = 0.0f;
        }
        __syncthreads();
    }
}

__global__ void palette_kernel(float* __restrict__ out) {
    int t = threadIdx.x;
    if (t < NB * NK) {
        float d = gDen[t] + EPSV;
#pragma unroll
        for (int c = 0; c < 3; c++) {
            float v = gNum[t * 3 + c] / d;
            gPal[t * 3 + c] = v;
            out[OFF_P + (size_t)t * 3 + c] = v;
        }
    }
}

__global__ __launch_bounds__(256) void transform_kernel(float* __restrict__ out) {
    __shared__ float pal[NB * NK * 3];
    int t = threadIdx.x;
    if (t < NB * NK * 3) pal[t] = gPal[t];
    __syncthreads();

    int g = blockIdx.x * 256 + t;
    int b = g / HW;
    int p = g % HW;
    int am = gArg[g];

    const float* pp = &pal[(b * NK + am) * 3];
    float* op = out + OFF_T + (size_t)b * 3 * HW + p;
    op[0]              = pp[0];
    op[(size_t)HW]     = pp[1];
    op[(size_t)2 * HW] = pp[2];
}

extern "C" void kernel_launch(void* const* d_in, const int* in_sizes, int n_in,
                              void* d_out, int out_size) {
    const float* img  = (const float*)d_in[0];
    const float* feat = (const float*)d_in[1];
    const float* W1   = (const float*)d_in[2];
    const float* b1   = (const float*)d_in[3];
    const float* W2   = (const float*)d_in[4];
    float* out = (float*)d_out;

    cudaFuncSetAttribute(main_kernel, cudaFuncAttributeMaxDynamicSharedMemorySize, SMEM_BYTES);

    zero_kernel<<<1, 256>>>();
    main_kernel<<<NCTA, 256, SMEM_BYTES>>>(img, feat, W1, b1, W2, out);
    palette_kernel<<<1, 64>>>(out);
    transform_kernel<<<NB * HW / 256, 256>>>(out);
}

// round 11
// speedup vs baseline: 2.3893x; 1.0321x over previous
#include <cuda_runtime.h>
#include <cuda_fp16.h>
#include <math.h>

typedef unsigned int        u32;
typedef unsigned long long  u64;

#define HW     (512*512)
#define NB     4
#define NC     64
#define HID    128
#define NK     16
#define SOFTEN 10000.0f
#define EPSV   1e-8f

#define TILE        128
#define NTILES      (NB * HW / TILE)   // 8192
#define NCTA        148
#define THREADS     512

// out layout: transformed_img [4,3,512,512] | m [4,16,512,512] | palette [4,16,3,1,1]
#define OFF_T  ((size_t)0)
#define OFF_M  ((size_t)NB * 3 * HW)
#define OFF_P  (OFF_M + (size_t)NB * NK * HW)

// ---- dynamic smem layout (bytes) ----
#define A_ROW     528                          // 132 f32 per c-row (128 px + pad)
#define A_BUF     (NC * A_ROW)                 // 33792
#define SM_A      0                            // 2 bufs = 67584
#define SM_AH     67584                        // 32 c2-rows x 136 u32 (half2) = 17408
#define SM_AL     84992                        // 17408
#define SM_W1F    102400                       // 4ks x 16nb x 32 lane x uint4 = 32768
#define SM_W2F    135168                       // 8ks x 2nb x 32 lane x uint4 = 8192
#define SM_SLB    143360                       // 4nw x 128px x 20 f32 = 40960
#define SM_SNUM   184320                       // 192
#define SM_SDEN   184512                       // 64
#define SMEM_BYTES 184576

// ---- scratch (no allocations allowed) ----
__device__ float         gNum[NB * NK * 3];
__device__ float         gDen[NB * NK];
__device__ float         gPal[NB * NK * 3];
__device__ unsigned char gArg[NB * HW];

__device__ __forceinline__ u32 smem_u32(const void* p) {
    u32 a;
    asm("{ .reg .u64 t; cvta.to.shared.u64 t, %1; cvt.u32.u64 %0, t; }" : "=r"(a) : "l"(p));
    return a;
}
#define CP_ASYNC16(dst, src) \
    asm volatile("cp.async.ca.shared.global [%0], [%1], 16;" :: "r"(dst), "l"(src) : "memory")
#define CP_COMMIT()  asm volatile("cp.async.commit_group;" ::: "memory")
#define CP_WAIT0()   asm volatile("cp.async.wait_group 0;" ::: "memory")

// fp16 m16n8k16 HMMA, f32 accumulate
__device__ __forceinline__ void mma16(float d[4], u32 a0, u32 a1, u32 a2, u32 a3,
                                      u32 b0, u32 b1) {
    asm volatile(
        "mma.sync.aligned.m16n8k16.row.col.f32.f16.f16.f32 "
        "{%0,%1,%2,%3},{%4,%5,%6,%7},{%8,%9},{%0,%1,%2,%3};"
        : "+f"(d[0]), "+f"(d[1]), "+f"(d[2]), "+f"(d[3])
        : "r"(a0), "r"(a1), "r"(a2), "r"(a3), "r"(b0), "r"(b1));
}

// exact 2-way fp16 split of a float pair: (x,y) -> hi fp16x2 + lo fp16x2
__device__ __forceinline__ void split2(float x, float y, u32& hi, u32& lo) {
    __half2 h = __floats2half2_rn(x, y);
    float2  b = __half22float2(h);
    __half2 l = __floats2half2_rn(x - b.x, y - b.y);
    hi = *(u32*)&h;
    lo = *(u32*)&l;
}

__global__ void zero_kernel() {
    int t = threadIdx.x;
    if (t < NB * NK * 3) gNum[t] = 0.0f;
    if (t < NB * NK)     gDen[t] = 0.0f;
}

// ============================ main persistent kernel ============================
__global__ __launch_bounds__(THREADS, 1) void main_kernel(
    const float* __restrict__ img,
    const float* __restrict__ feat,
    const float* __restrict__ b1,
    const float* __restrict__ W1,
    const float* __restrict__ W2,
    float* __restrict__ out)
{
    extern __shared__ char sm[];
    const int tid = threadIdx.x;
    const int wid = tid >> 5;
    const int lid = tid & 31;
    const int mwarp = wid & 3;        // px range: mwarp*32 .. +31
    const int nwarp = wid >> 2;       // o range:  nwarp*32 .. +31
    const int lq = lid & 3;
    const int lg = lid >> 2;

    if (tid < NK * 3) *(float*)(sm + SM_SNUM + tid * 4) = 0.0f;
    if (tid < NK)     *(float*)(sm + SM_SDEN + tid * 4) = 0.0f;

    // ---- stage W1/W2 fragments (once per CTA) ----
    {
        uint4* W1F = (uint4*)(sm + SM_W1F);
        for (int e = tid; e < 4 * 16 * 32; e += THREADS) {
            int ks = e >> 9, nb = (e >> 5) & 15, ln = e & 31;
            int o  = nb * 8 + (ln >> 2);
            int c0 = ks * 16 + 2 * (ln & 3);
            u32 b0h, b0l, b1h, b1l;
            split2(W1[o * NC + c0],     W1[o * NC + c0 + 1], b0h, b0l);
            split2(W1[o * NC + c0 + 8], W1[o * NC + c0 + 9], b1h, b1l);
            W1F[e] = make_uint4(b0h, b1h, b0l, b1l);
        }
        uint4* W2F = (uint4*)(sm + SM_W2F);
        for (int e = tid; e < 8 * 2 * 32; e += THREADS) {
            int ks2 = e >> 6, nbk = (e >> 5) & 1, ln = e & 31;
            int cls = nbk * 8 + (ln >> 2);
            int o0  = ks2 * 16 + 2 * (ln & 3);
            u32 b0h, b0l, b1h, b1l;
            split2(W2[cls * HID + o0],     W2[cls * HID + o0 + 1], b0h, b0l);
            split2(W2[cls * HID + o0 + 8], W2[cls * HID + o0 + 9], b1h, b1l);
            W2F[e] = make_uint4(b0h, b1h, b0l, b1l);
        }
    }

    // per-lane bias pairs: o = nwarp*32 + j*8 + 2*lq + {0,1}
    float2 bias2[4];
#pragma unroll
    for (int j = 0; j < 4; j++)
        bias2[j] = *(const float2*)(b1 + nwarp * 32 + j * 8 + 2 * lq);

    __syncthreads();

    const int bx = blockIdx.x;
    const int niter = (NTILES - 1 - bx) / NCTA + 1;
    const u32 smA = smem_u32(sm + SM_A);

    // prologue: prefetch tile 0 (c-major fp32, row stride 528B)
    {
        const int t0 = bx;
        const float* fb = feat + (size_t)(t0 >> 11) * NC * HW + (t0 & 2047) * TILE;
#pragma unroll
        for (int r = 0; r < 4; r++) {
            int i = tid + THREADS * r;
            int c = i >> 5, ci = i & 31;
            CP_ASYNC16(smA + c * A_ROW + ci * 16, fb + (size_t)c * HW + ci * 4);
        }
        CP_COMMIT();
    }

    const uint4* W1F = (const uint4*)(sm + SM_W1F);
    const uint4* W2F = (const uint4*)(sm + SM_W2F);
    u32* AH = (u32*)(sm + SM_AH);
    u32* AL = (u32*)(sm + SM_AL);
    float* slb = (float*)(sm + SM_SLB);

    for (int it = 0; it < niter; it++) {
        const int t  = bx + NCTA * it;
        const int bb = t >> 11;
        const int p0 = (t & 2047) * TILE;
        const int buf = it & 1;

        CP_WAIT0();
        __syncthreads();

        if (it + 1 < niter) {
            const int tn = bx + NCTA * (it + 1);
            const float* fb = feat + (size_t)(tn >> 11) * NC * HW + (tn & 2047) * TILE;
            const u32 dst = smA + (buf ^ 1) * A_BUF;
#pragma unroll
            for (int r = 0; r < 4; r++) {
                int i = tid + THREADS * r;
                int c = i >> 5, ci = i & 31;
                CP_ASYNC16(dst + c * A_ROW + ci * 16, fb + (size_t)c * HW + ci * 4);
            }
            CP_COMMIT();
        }

        // ---- A prep: split fp32 tile -> AH/AL half2 (c-pair packed), once ----
        {
            const float* Ab = (const float*)(sm + SM_A + buf * A_BUF);
#pragma unroll
            for (int r = 0; r < 8; r++) {
                int idx = tid + THREADS * r;          // 4096 = 32 c2 x 128 px
                int c2 = idx >> 7, px = idx & 127;
                float f0 = Ab[(2 * c2)     * 132 + px];
                float f1 = Ab[(2 * c2 + 1) * 132 + px];
                u32 hi, lo;
                split2(f0, f1, hi, lo);
                AH[c2 * 136 + px] = hi;
                AL[c2 * 136 + px] = lo;
            }
        }
        __syncthreads();

        // ================= GEMM1 (tensor): h = feat * W1^T, fp16 3-term ==========
        float d[2][4][4];
#pragma unroll
        for (int mb = 0; mb < 2; mb++)
#pragma unroll
            for (int j = 0; j < 4; j++)
#pragma unroll
                for (int r = 0; r < 4; r++) d[mb][j][r] = 0.0f;

#pragma unroll
        for (int ks = 0; ks < 4; ks++) {
            u32 ah[2][4], al[2][4];
#pragma unroll
            for (int mb = 0; mb < 2; mb++) {
                const int pxr = mwarp * 32 + mb * 16 + lg;
                const int c2  = ks * 8 + lq;
                ah[mb][0] = AH[c2 * 136 + pxr];
                ah[mb][1] = AH[c2 * 136 + pxr + 8];
                ah[mb][2] = AH[(c2 + 4) * 136 + pxr];
                ah[mb][3] = AH[(c2 + 4) * 136 + pxr + 8];
                al[mb][0] = AL[c2 * 136 + pxr];
                al[mb][1] = AL[c2 * 136 + pxr + 8];
                al[mb][2] = AL[(c2 + 4) * 136 + pxr];
                al[mb][3] = AL[(c2 + 4) * 136 + pxr + 8];
            }
#pragma unroll
            for (int j = 0; j < 4; j++) {
                uint4 bq = W1F[(ks * 16 + nwarp * 4 + j) * 32 + lid];
#pragma unroll
                for (int mb = 0; mb < 2; mb++) {
                    mma16(d[mb][j], ah[mb][0], ah[mb][1], ah[mb][2], ah[mb][3], bq.x, bq.y);
                    mma16(d[mb][j], ah[mb][0], ah[mb][1], ah[mb][2], ah[mb][3], bq.z, bq.w);
                    mma16(d[mb][j], al[mb][0], al[mb][1], al[mb][2], al[mb][3], bq.x, bq.y);
                }
            }
        }

        // ================= GEMM2 (tensor): logits = relu(h+b1) * W2^T =============
        float l2[2][2][4];
#pragma unroll
        for (int mb = 0; mb < 2; mb++)
#pragma unroll
            for (int nbk = 0; nbk < 2; nbk++)
#pragma unroll
                for (int r = 0; r < 4; r++) l2[mb][nbk][r] = 0.0f;

#pragma unroll
        for (int s = 0; s < 2; s++) {
            const int ks2g = nwarp * 2 + s;
#pragma unroll
            for (int mb = 0; mb < 2; mb++) {
                u32 a0h, a0l, a1h, a1l, a2h, a2l, a3h, a3l;
                {
                    const int j = 2 * s;
                    float r0 = fmaxf(d[mb][j][0] + bias2[j].x, 0.0f);
                    float r1 = fmaxf(d[mb][j][1] + bias2[j].y, 0.0f);
                    float r2 = fmaxf(d[mb][j][2] + bias2[j].x, 0.0f);
                    float r3 = fmaxf(d[mb][j][3] + bias2[j].y, 0.0f);
                    split2(r0, r1, a0h, a0l);
                    split2(r2, r3, a1h, a1l);
                }
                {
                    const int j = 2 * s + 1;
                    float r0 = fmaxf(d[mb][j][0] + bias2[j].x, 0.0f);
                    float r1 = fmaxf(d[mb][j][1] + bias2[j].y, 0.0f);
                    float r2 = fmaxf(d[mb][j][2] + bias2[j].x, 0.0f);
                    float r3 = fmaxf(d[mb][j][3] + bias2[j].y, 0.0f);
                    split2(r0, r1, a2h, a2l);
                    split2(r2, r3, a3h, a3l);
                }
#pragma unroll
                for (int nbk = 0; nbk < 2; nbk++) {
                    uint4 w = W2F[(ks2g * 2 + nbk) * 32 + lid];
                    mma16(l2[mb][nbk], a0h, a1h, a2h, a3h, w.x, w.y);
                    mma16(l2[mb][nbk], a0h, a1h, a2h, a3h, w.z, w.w);
                    mma16(l2[mb][nbk], a0l, a1l, a2l, a3l, w.x, w.y);
                }
            }
        }

        // ---- write partial logits (this warp's 32 o) to slb[nwarp] ----
#pragma unroll
        for (int mb = 0; mb < 2; mb++) {
            const int r1 = mwarp * 32 + mb * 16 + lg;
#pragma unroll
            for (int nbk = 0; nbk < 2; nbk++) {
                const int cls = nbk * 8 + 2 * lq;
                *(float2*)&slb[(nwarp * 128 + r1) * 20 + cls] =
                    make_float2(l2[mb][nbk][0], l2[mb][nbk][1]);
                *(float2*)&slb[(nwarp * 128 + r1 + 8) * 20 + cls] =
                    make_float2(l2[mb][nbk][2], l2[mb][nbk][3]);
            }
        }
        __syncthreads();

        // ================= epilogue: 4 lanes per pixel (k quarters) ===============
        {
            const int pxl = wid * 8 + (lid & 7);
            const int kq  = lid >> 3;              // k = kq*4 .. kq*4+3
            const int p   = p0 + pxl;

            float4 v4 = make_float4(0.f, 0.f, 0.f, 0.f);
#pragma unroll
            for (int nw = 0; nw < 4; nw++) {
                float4 pv = *(float4*)&slb[(nw * 128 + pxl) * 20 + kq * 4];
                v4.x += pv.x; v4.y += pv.y; v4.z += pv.z; v4.w += pv.w;
            }
            float v[4] = {v4.x, v4.y, v4.z, v4.w};

            float mx = v[0];
            int   am = kq * 4;
#pragma unroll
            for (int k = 1; k < 4; k++)
                if (v[k] > mx) { mx = v[k]; am = kq * 4 + k; }

#pragma unroll
            for (int off = 8; off <= 16; off <<= 1) {
                float omx = __shfl_xor_sync(0xffffffffu, mx, off);
                int   oam = __shfl_xor_sync(0xffffffffu, am, off);
                bool take = (omx > mx) || (omx == mx && oam < am);
                mx = take ? omx : mx;
                am = take ? oam : am;
            }

            float e[4], s = 0.0f;
#pragma unroll
            for (int k = 0; k < 4; k++) { e[k] = __expf(SOFTEN * (v[k] - mx)); s += e[k]; }
            s += __shfl_xor_sync(0xffffffffu, s, 8);
            s += __shfl_xor_sync(0xffffffffu, s, 16);
            const float inv = 1.0f / s;

            float* mo = out + OFF_M + (size_t)bb * NK * HW + (size_t)kq * 4 * HW + p;
#pragma unroll
            for (int k = 0; k < 4; k++) mo[(size_t)k * HW] = e[k] * inv;

            if (kq == 0) {
                gArg[(size_t)bb * HW + p] = (unsigned char)am;
                const float* ip = img + (size_t)bb * 3 * HW + p;
                float* snum = (float*)(sm + SM_SNUM);
                float* sden = (float*)(sm + SM_SDEN);
                atomicAdd(&snum[am * 3 + 0], __ldg(ip));
                atomicAdd(&snum[am * 3 + 1], __ldg(ip + HW));
                atomicAdd(&snum[am * 3 + 2], __ldg(ip + 2 * HW));
                atomicAdd(&sden[am], 1.0f);
            }
        }
        __syncthreads();
        if (tid < NK * 3) {
            float* snum = (float*)(sm + SM_SNUM);
            atomicAdd(&gNum[bb * NK * 3 + tid], snum[tid]);
            snum[tid] = 0.0f;
        }
        if (tid < NK) {
            float* sden = (float*)(sm + SM_SDEN);
            atomicAdd(&gDen[bb * NK + tid], sden[tid]);
            sden[tid] = 0.0f;
        }
        __syncthreads();
    }
}

__global__ void palette_kernel(float* __restrict__ out) {
    int t = threadIdx.x;
    if (t < NB * NK) {
        float d = gDen[t] + EPSV;
#pragma unroll
        for (int c = 0; c < 3; c++) {
            float v = gNum[t * 3 + c] / d;
            gPal[t * 3 + c] = v;
            out[OFF_P + (size_t)t * 3 + c] = v;
        }
    }
}

__global__ __launch_bounds__(256) void transform_kernel(float* __restrict__ out) {
    __shared__ float pal[NB * NK * 3];
    int t = threadIdx.x;
    if (t < NB * NK * 3) pal[t] = gPal[t];
    __syncthreads();

    int g = blockIdx.x * 256 + t;
    int b = g / HW;
    int p = g % HW;
    int am = gArg[g];

    const float* pp = &pal[(b * NK + am) * 3];
    float* op = out + OFF_T + (size_t)b * 3 * HW + p;
    op[0]              = pp[0];
    op[(size_t)HW]     = pp[1];
    op[(size_t)2 * HW] = pp[2];
}

extern "C" void kernel_launch(void* const* d_in, const int* in_sizes, int n_in,
                              void* d_out, int out_size) {
    const float* img  = (const float*)d_in[0];
    const float* feat = (const float*)d_in[1];
    const float* W1   = (const float*)d_in[2];
    const float* b1   = (const float*)d_in[3];
    const float* W2   = (const float*)d_in[4];
    float* out = (float*)d_out;

    cudaFuncSetAttribute(main_kernel, cudaFuncAttributeMaxDynamicSharedMemorySize, SMEM_BYTES);

    zero_kernel<<<1, 256>>>();
    main_kernel<<<NCTA, THREADS, SMEM_BYTES>>>(img, feat, b1, W1, W2, out);
    palette_kernel<<<1, 64>>>(out);
    transform_kernel<<<NB * HW / 256, 256>>>(out);
}

// round 13
// speedup vs baseline: 3.5455x; 1.4839x over previous
#include <cuda_runtime.h>
#include <cuda_fp16.h>
#include <math.h>

typedef unsigned int        u32;
typedef unsigned long long  u64;

#define HW     (512*512)
#define NB     4
#define NC     64
#define HID    128
#define NK     16
#define SOFTEN 10000.0f
#define EPSV   1e-8f

#define TILE        128
#define NTILES      (NB * HW / TILE)   // 8192
#define NCTA        296                // 2 CTAs per SM
#define THREADS     256

// out layout: transformed_img [4,3,512,512] | m [4,16,512,512] | palette [4,16,3,1,1]
#define OFF_T  ((size_t)0)
#define OFF_M  ((size_t)NB * 3 * HW)
#define OFF_P  (OFF_M + (size_t)NB * NK * HW)

// ---- dynamic smem layout (bytes), total 96512 (2 CTAs fit in 228KB/SM) ----
#define SM_AH     0                      // 32 c2-rows x 136 u32 = 17408
#define SM_AL     17408                  // 17408
#define SM_W1F    34816                  // 4ks x 16nb x 32 lane x uint4 = 32768
#define SM_W2F    67584                  // 8ks x 2nb x 32 lane x uint4 = 8192
#define SM_SLB    75776                  // 2nw x 128px x 20 f32 = 20480
#define SM_SNUM   96256                  // 192
#define SM_SDEN   96448                  // 64
#define SMEM_BYTES 96512

// ---- scratch (no allocations allowed) ----
__device__ float         gNum[NB * NK * 3];
__device__ float         gDen[NB * NK];
__device__ float         gPal[NB * NK * 3];
__device__ unsigned char gArg[NB * HW];

// fp16 m16n8k16 HMMA, f32 accumulate
__device__ __forceinline__ void mma16(float d[4], u32 a0, u32 a1, u32 a2, u32 a3,
                                      u32 b0, u32 b1) {
    asm volatile(
        "mma.sync.aligned.m16n8k16.row.col.f32.f16.f16.f32 "
        "{%0,%1,%2,%3},{%4,%5,%6,%7},{%8,%9},{%0,%1,%2,%3};"
        : "+f"(d[0]), "+f"(d[1]), "+f"(d[2]), "+f"(d[3])
        : "r"(a0), "r"(a1), "r"(a2), "r"(a3), "r"(b0), "r"(b1));
}

// exact 2-way fp16 split of a float pair: (x,y) -> hi fp16x2 + lo fp16x2
__device__ __forceinline__ void split2(float x, float y, u32& hi, u32& lo) {
    __half2 h = __floats2half2_rn(x, y);
    float2  b = __half22float2(h);
    __half2 l = __floats2half2_rn(x - b.x, y - b.y);
    hi = *(u32*)&h;
    lo = *(u32*)&l;
}

__global__ void zero_kernel() {
    int t = threadIdx.x;
    if (t < NB * NK * 3) gNum[t] = 0.0f;
    if (t < NB * NK)     gDen[t] = 0.0f;
}

// ======================= main kernel: 2 CTAs per SM =========================
__global__ __launch_bounds__(THREADS, 2) void main_kernel(
    const float* __restrict__ img,
    const float* __restrict__ feat,
    const float* __restrict__ b1,
    const float* __restrict__ W1,
    const float* __restrict__ W2,
    float* __restrict__ out)
{
    extern __shared__ char sm[];
    const int tid = threadIdx.x;
    const int wid = tid >> 5;
    const int lid = tid & 31;
    const int mwarp = wid & 3;        // px range: mwarp*32 .. +31
    const int nwarp = wid >> 2;       // o range:  nwarp*64 .. +63
    const int lq = lid & 3;
    const int lg = lid >> 2;

    if (tid < NK * 3) *(float*)(sm + SM_SNUM + tid * 4) = 0.0f;
    if (tid < NK)     *(float*)(sm + SM_SDEN + tid * 4) = 0.0f;

    // ---- stage W1/W2 fragments (once per CTA) ----
    {
        uint4* W1F = (uint4*)(sm + SM_W1F);
        for (int e = tid; e < 4 * 16 * 32; e += THREADS) {
            int ks = e >> 9, nb = (e >> 5) & 15, ln = e & 31;
            int o  = nb * 8 + (ln >> 2);
            int c0 = ks * 16 + 2 * (ln & 3);
            u32 b0h, b0l, b1h, b1l;
            split2(W1[o * NC + c0],     W1[o * NC + c0 + 1], b0h, b0l);
            split2(W1[o * NC + c0 + 8], W1[o * NC + c0 + 9], b1h, b1l);
            W1F[e] = make_uint4(b0h, b1h, b0l, b1l);
        }
        uint4* W2F = (uint4*)(sm + SM_W2F);
        for (int e = tid; e < 8 * 2 * 32; e += THREADS) {
            int ks2 = e >> 6, nbk = (e >> 5) & 1, ln = e & 31;
            int cls = nbk * 8 + (ln >> 2);
            int o0  = ks2 * 16 + 2 * (ln & 3);
            u32 b0h, b0l, b1h, b1l;
            split2(W2[cls * HID + o0],     W2[cls * HID + o0 + 1], b0h, b0l);
            split2(W2[cls * HID + o0 + 8], W2[cls * HID + o0 + 9], b1h, b1l);
            W2F[e] = make_uint4(b0h, b1h, b0l, b1l);
        }
    }

    // per-lane bias pairs from GLOBAL b1 (no smem race): o = nwarp*64 + j*8 + 2*lq
    float2 bias2[8];
#pragma unroll
    for (int j = 0; j < 8; j++)
        bias2[j] = *(const float2*)(b1 + nwarp * 64 + j * 8 + 2 * lq);

    __syncthreads();

    const uint4* W1F = (const uint4*)(sm + SM_W1F);
    const uint4* W2F = (const uint4*)(sm + SM_W2F);
    u32* AH = (u32*)(sm + SM_AH);
    u32* AL = (u32*)(sm + SM_AL);
    float* slb  = (float*)(sm + SM_SLB);
    float* snum = (float*)(sm + SM_SNUM);
    float* sden = (float*)(sm + SM_SDEN);

    for (int t = blockIdx.x; t < NTILES; t += NCTA) {
        const int bb = t >> 11;
        const int p0 = (t & 2047) * TILE;

        // ---- load + split feat tile: LDG -> fp16 split -> STS (AH/AL) ----
        {
            const float* fb = feat + (size_t)bb * NC * HW + p0;
#pragma unroll
            for (int r = 0; r < 4; r++) {
                int idx = tid + THREADS * r;       // 1024 = 32 c2 x 32 px4
                int c2 = idx >> 5, px4 = idx & 31;
                float4 f0 = *(const float4*)(fb + (size_t)(2 * c2)     * HW + px4 * 4);
                float4 f1 = *(const float4*)(fb + (size_t)(2 * c2 + 1) * HW + px4 * 4);
                uint4 hi, lo;
                split2(f0.x, f1.x, hi.x, lo.x);
                split2(f0.y, f1.y, hi.y, lo.y);
                split2(f0.z, f1.z, hi.z, lo.z);
                split2(f0.w, f1.w, hi.w, lo.w);
                *(uint4*)(AH + c2 * 136 + px4 * 4) = hi;
                *(uint4*)(AL + c2 * 136 + px4 * 4) = lo;
            }
        }
        __syncthreads();

        // ================= GEMM1 (tensor): h = feat * W1^T, fp16 3-term ==========
        float d[2][8][4];
#pragma unroll
        for (int mb = 0; mb < 2; mb++)
#pragma unroll
            for (int j = 0; j < 8; j++)
#pragma unroll
                for (int r = 0; r < 4; r++) d[mb][j][r] = 0.0f;

#pragma unroll
        for (int ks = 0; ks < 4; ks++) {
            u32 ah[2][4], al[2][4];
#pragma unroll
            for (int mb = 0; mb < 2; mb++) {
                const int pxr = mwarp * 32 + mb * 16 + lg;
                const int c2  = ks * 8 + lq;
                ah[mb][0] = AH[c2 * 136 + pxr];
                ah[mb][1] = AH[c2 * 136 + pxr + 8];
                ah[mb][2] = AH[(c2 + 4) * 136 + pxr];
                ah[mb][3] = AH[(c2 + 4) * 136 + pxr + 8];
                al[mb][0] = AL[c2 * 136 + pxr];
                al[mb][1] = AL[c2 * 136 + pxr + 8];
                al[mb][2] = AL[(c2 + 4) * 136 + pxr];
                al[mb][3] = AL[(c2 + 4) * 136 + pxr + 8];
            }
#pragma unroll
            for (int j = 0; j < 8; j++) {
                uint4 bq = W1F[(ks * 16 + nwarp * 8 + j) * 32 + lid];
#pragma unroll
                for (int mb = 0; mb < 2; mb++) {
                    mma16(d[mb][j], ah[mb][0], ah[mb][1], ah[mb][2], ah[mb][3], bq.x, bq.y);
                    mma16(d[mb][j], ah[mb][0], ah[mb][1], ah[mb][2], ah[mb][3], bq.z, bq.w);
                    mma16(d[mb][j], al[mb][0], al[mb][1], al[mb][2], al[mb][3], bq.x, bq.y);
                }
            }
        }

        // ================= GEMM2 (tensor): logits = relu(h+b1) * W2^T =============
        float l2[2][2][4];
#pragma unroll
        for (int mb = 0; mb < 2; mb++)
#pragma unroll
            for (int nbk = 0; nbk < 2; nbk++)
#pragma unroll
                for (int r = 0; r < 4; r++) l2[mb][nbk][r] = 0.0f;

#pragma unroll
        for (int s = 0; s < 4; s++) {
            const int ks2g = nwarp * 4 + s;
#pragma unroll
            for (int mb = 0; mb < 2; mb++) {
                u32 a0h, a0l, a1h, a1l, a2h, a2l, a3h, a3l;
                {
                    const int j = 2 * s;
                    float r0 = fmaxf(d[mb][j][0] + bias2[j].x, 0.0f);
                    float r1 = fmaxf(d[mb][j][1] + bias2[j].y, 0.0f);
                    float r2 = fmaxf(d[mb][j][2] + bias2[j].x, 0.0f);
                    float r3 = fmaxf(d[mb][j][3] + bias2[j].y, 0.0f);
                    split2(r0, r1, a0h, a0l);
                    split2(r2, r3, a1h, a1l);
                }
                {
                    const int j = 2 * s + 1;
                    float r0 = fmaxf(d[mb][j][0] + bias2[j].x, 0.0f);
                    float r1 = fmaxf(d[mb][j][1] + bias2[j].y, 0.0f);
                    float r2 = fmaxf(d[mb][j][2] + bias2[j].x, 0.0f);
                    float r3 = fmaxf(d[mb][j][3] + bias2[j].y, 0.0f);
                    split2(r0, r1, a2h, a2l);
                    split2(r2, r3, a3h, a3l);
                }
#pragma unroll
                for (int nbk = 0; nbk < 2; nbk++) {
                    uint4 w = W2F[(ks2g * 2 + nbk) * 32 + lid];
                    mma16(l2[mb][nbk], a0h, a1h, a2h, a3h, w.x, w.y);
                    mma16(l2[mb][nbk], a0h, a1h, a2h, a3h, w.z, w.w);
                    mma16(l2[mb][nbk], a0l, a1l, a2l, a3l, w.x, w.y);
                }
            }
        }

        // ---- write partial logits (this warp's 64 o) to slb ----
#pragma unroll
        for (int mb = 0; mb < 2; mb++) {
            const int r1 = mwarp * 32 + mb * 16 + lg;
#pragma unroll
            for (int nbk = 0; nbk < 2; nbk++) {
                const int cls = nbk * 8 + 2 * lq;
                *(float2*)&slb[(nwarp * 128 + r1) * 20 + cls] =
                    make_float2(l2[mb][nbk][0], l2[mb][nbk][1]);
                *(float2*)&slb[(nwarp * 128 + r1 + 8) * 20 + cls] =
                    make_float2(l2[mb][nbk][2], l2[mb][nbk][3]);
            }
        }
        __syncthreads();

        // ================= epilogue: 2 lanes per pixel =============================
        {
            const int pxl = wid * 16 + (lid & 15);
            const int kh  = lid >> 4;              // k-half: 0 -> k 0..7, 1 -> 8..15
            const int p   = p0 + pxl;

            float4 vA0 = *(float4*)&slb[pxl * 20 + kh * 8];
            float4 vA1 = *(float4*)&slb[pxl * 20 + kh * 8 + 4];
            float4 vB0 = *(float4*)&slb[(128 + pxl) * 20 + kh * 8];
            float4 vB1 = *(float4*)&slb[(128 + pxl) * 20 + kh * 8 + 4];
            float v[8] = {vA0.x + vB0.x, vA0.y + vB0.y, vA0.z + vB0.z, vA0.w + vB0.w,
                          vA1.x + vB1.x, vA1.y + vB1.y, vA1.z + vB1.z, vA1.w + vB1.w};

            float mx = v[0];
            int   am = kh * 8;
#pragma unroll
            for (int k = 1; k < 8; k++)
                if (v[k] > mx) { mx = v[k]; am = kh * 8 + k; }

            float mo_ = __shfl_xor_sync(0xffffffffu, mx, 16);
            int   ao_ = __shfl_xor_sync(0xffffffffu, am, 16);
            bool take = (mo_ > mx) || (mo_ == mx && ao_ < am);
            float gmax = take ? mo_ : mx;
            int   gam  = take ? ao_ : am;

            float e[8], s = 0.0f;
#pragma unroll
            for (int k = 0; k < 8; k++) { e[k] = __expf(SOFTEN * (v[k] - gmax)); s += e[k]; }
            s += __shfl_xor_sync(0xffffffffu, s, 16);
            const float inv = 1.0f / s;

            float* mo = out + OFF_M + (size_t)bb * NK * HW + (size_t)kh * 8 * HW + p;
#pragma unroll
            for (int k = 0; k < 8; k++) mo[(size_t)k * HW] = e[k] * inv;

            if (kh == 0) {
                gArg[(size_t)bb * HW + p] = (unsigned char)gam;
                const float* ip = img + (size_t)bb * 3 * HW + p;
                atomicAdd(&snum[gam * 3 + 0], __ldg(ip));
                atomicAdd(&snum[gam * 3 + 1], __ldg(ip + HW));
                atomicAdd(&snum[gam * 3 + 2], __ldg(ip + 2 * HW));
                atomicAdd(&sden[gam], 1.0f);
            }
        }
        __syncthreads();
        if (tid < NK * 3) {
            atomicAdd(&gNum[bb * NK * 3 + tid], snum[tid]);
            snum[tid] = 0.0f;
        }
        if (tid < NK) {
            atomicAdd(&gDen[bb * NK + tid], sden[tid]);
            sden[tid] = 0.0f;
        }
        __syncthreads();   // snum/sden reset + AH/AL reuse ordered before next tile
    }
}

__global__ void palette_kernel(float* __restrict__ out) {
    int t = threadIdx.x;
    if (t < NB * NK) {
        float d = gDen[t] + EPSV;
#pragma unroll
        for (int c = 0; c < 3; c++) {
            float v = gNum[t * 3 + c] / d;
            gPal[t * 3 + c] = v;
            out[OFF_P + (size_t)t * 3 + c] = v;
        }
    }
}

__global__ __launch_bounds__(256) void transform_kernel(float* __restrict__ out) {
    __shared__ float pal[NB * NK * 3];
    int t = threadIdx.x;
    if (t < NB * NK * 3) pal[t] = gPal[t];
    __syncthreads();

    int g = blockIdx.x * 256 + t;
    int b = g / HW;
    int p = g % HW;
    int am = gArg[g];

    const float* pp = &pal[(b * NK + am) * 3];
    float* op = out + OFF_T + (size_t)b * 3 * HW + p;
    op[0]              = pp[0];
    op[(size_t)HW]     = pp[1];
    op[(size_t)2 * HW] = pp[2];
}

extern "C" void kernel_launch(void* const* d_in, const int* in_sizes, int n_in,
                              void* d_out, int out_size) {
    const float* img  = (const float*)d_in[0];
    const float* feat = (const float*)d_in[1];
    const float* W1   = (const float*)d_in[2];
    const float* b1   = (const float*)d_in[3];
    const float* W2   = (const float*)d_in[4];
    float* out = (float*)d_out;

    cudaFuncSetAttribute(main_kernel, cudaFuncAttributeMaxDynamicSharedMemorySize, SMEM_BYTES);

    zero_kernel<<<1, 256>>>();
    main_kernel<<<NCTA, THREADS, SMEM_BYTES>>>(img, feat, b1, W1, W2, out);
    palette_kernel<<<1, 64>>>(out);
    transform_kernel<<<NB * HW / 256, 256>>>(out);
}